// round 3
// baseline (speedup 1.0000x reference)
#include <cuda_runtime.h>
#include <cuda_bf16.h>
#include <mma.h>
#include <cstdint>
#include <cstddef>

using namespace nvcuda;

#define BB 512
#define CC 256
#define NNPTS 500000
#define HH 1024
#define CAND_CAP (8*1024*1024)
#define STAGE_CAP 4096
#define EPS_SCREEN 3.0f

// ---------------- static device scratch (no dynamic allocation allowed) -----
__device__ unsigned int        g_minval[BB];          // ordered-encoded approx running min
__device__ unsigned long long  g_exact[BB];           // packed (fp32 dist bits << 20) | index
__device__ unsigned int        g_cands[CAND_CAP];     // packed (row << 20) | index
__device__ int                 g_cand_cnt;
__device__ float               g_scratch[BB*CC + 8*BB*HH];

// ---------------- helpers ---------------------------------------------------
__device__ __forceinline__ unsigned int fenc(float f) {
    unsigned int b = __float_as_uint(f);
    return (b & 0x80000000u) ? ~b : (b | 0x80000000u);
}
__device__ __forceinline__ float fdec(unsigned int u) {
    unsigned int b = (u & 0x80000000u) ? (u & 0x7FFFFFFFu) : ~u;
    return __uint_as_float(b);
}
__device__ __forceinline__ void st8bf(__nv_bfloat16* d, float4 a, float4 b) {
    d[0]=__float2bfloat16(a.x); d[1]=__float2bfloat16(a.y);
    d[2]=__float2bfloat16(a.z); d[3]=__float2bfloat16(a.w);
    d[4]=__float2bfloat16(b.x); d[5]=__float2bfloat16(b.y);
    d[6]=__float2bfloat16(b.z); d[7]=__float2bfloat16(b.w);
}
__device__ __forceinline__ void split8(__nv_bfloat16* hp, __nv_bfloat16* lp,
                                       const float* v) {
    #pragma unroll
    for (int i = 0; i < 8; i++) {
        __nv_bfloat16 h = __float2bfloat16(v[i]);
        hp[i] = h;
        lp[i] = __float2bfloat16(v[i] - __bfloat162float(h));
    }
}

// ---------------- init ------------------------------------------------------
__global__ void k_init() {
    int t = blockIdx.x * blockDim.x + threadIdx.x;
    if (t < BB) {
        g_minval[t] = 0xFFFFFFFFu;
        g_exact[t]  = 0xFFFFFFFFFFFFFFFFull;
    }
    if (t == 0) g_cand_cnt = 0;
}

// ---------------- pass 1: bf16 WMMA screening GEMM + candidate collection ---
#define P1_SMEM 99392
__global__ void k_pass1(const float* __restrict__ codes, const float* __restrict__ cb) {
    extern __shared__ __align__(16) char smem[];
    float*         Cs    = (float*)smem;                      // 128*128 f32
    float*         norms = (float*)(smem + 65536);            // 128 f32
    unsigned int*  tmin  = (unsigned int*)(smem + 66048);     // 128 u32
    unsigned int*  stage = (unsigned int*)(smem + 66560);     // 4096 u32
    __nv_bfloat16* As    = (__nv_bfloat16*)(smem + 82944);    // 128x32
    __nv_bfloat16* Bs    = (__nv_bfloat16*)(smem + 91136);    // 128x32
    int*           s_cnt = (int*)(smem + 99328);
    int*           s_base= s_cnt + 1;

    int tid = threadIdx.x;
    int m0 = blockIdx.x * 128;   // code rows
    int n0 = blockIdx.y * 128;   // codebook rows

    if (tid < 128) { norms[tid] = 0.0f; tmin[tid] = 0xFFFFFFFFu; }
    if (tid == 0)  { *s_cnt = 0; }

    int wid = tid >> 5;
    int wm  = wid >> 1;   // 0..3 : 32 code rows each
    int wn  = wid & 1;    // 0..1 : 64 cb rows each

    wmma::fragment<wmma::accumulator,16,16,16,float> acc[2][4];
    #pragma unroll
    for (int i = 0; i < 2; i++)
        #pragma unroll
        for (int j = 0; j < 4; j++) wmma::fill_fragment(acc[i][j], 0.0f);

    int r = tid >> 1, q = tid & 1;

    for (int kc = 0; kc < CC; kc += 32) {
        __syncthreads();
        {   // A (codes) tile 128x32 -> bf16
            const float* ap = codes + (size_t)(m0 + r) * CC + kc + q * 16;
            float4 a0 = *(const float4*)(ap + 0);
            float4 a1 = *(const float4*)(ap + 4);
            float4 a2 = *(const float4*)(ap + 8);
            float4 a3 = *(const float4*)(ap + 12);
            st8bf(As + r * 32 + q * 16,     a0, a1);
            st8bf(As + r * 32 + q * 16 + 8, a2, a3);
        }
        {   // B (codebook) tile 128x32 -> bf16 + fp32 norm accumulation
            int gj = n0 + r;
            float4 b0 = make_float4(0.f,0.f,0.f,0.f), b1 = b0, b2 = b0, b3 = b0;
            if (gj < NNPTS) {
                const float* bp = cb + (size_t)gj * CC + kc + q * 16;
                b0 = *(const float4*)(bp + 0);
                b1 = *(const float4*)(bp + 4);
                b2 = *(const float4*)(bp + 8);
                b3 = *(const float4*)(bp + 12);
            }
            st8bf(Bs + r * 32 + q * 16,     b0, b1);
            st8bf(Bs + r * 32 + q * 16 + 8, b2, b3);
            if (gj < NNPTS) {
                float ss = b0.x*b0.x + b0.y*b0.y + b0.z*b0.z + b0.w*b0.w
                         + b1.x*b1.x + b1.y*b1.y + b1.z*b1.z + b1.w*b1.w
                         + b2.x*b2.x + b2.y*b2.y + b2.z*b2.z + b2.w*b2.w
                         + b3.x*b3.x + b3.y*b3.y + b3.z*b3.z + b3.w*b3.w;
                atomicAdd(&norms[r], ss);
            }
        }
        __syncthreads();
        #pragma unroll
        for (int kk = 0; kk < 32; kk += 16) {
            wmma::fragment<wmma::matrix_a,16,16,16,__nv_bfloat16,wmma::row_major> fa[2];
            wmma::fragment<wmma::matrix_b,16,16,16,__nv_bfloat16,wmma::col_major> fb[4];
            #pragma unroll
            for (int i = 0; i < 2; i++)
                wmma::load_matrix_sync(fa[i], As + (wm*32 + i*16)*32 + kk, 32);
            #pragma unroll
            for (int j = 0; j < 4; j++)
                wmma::load_matrix_sync(fb[j], Bs + (wn*64 + j*16)*32 + kk, 32);
            #pragma unroll
            for (int i = 0; i < 2; i++)
                #pragma unroll
                for (int j = 0; j < 4; j++)
                    wmma::mma_sync(acc[i][j], fa[i], fb[j], acc[i][j]);
        }
    }
    __syncthreads();
    #pragma unroll
    for (int i = 0; i < 2; i++)
        #pragma unroll
        for (int j = 0; j < 4; j++)
            wmma::store_matrix_sync(Cs + (wm*32 + i*16)*128 + wn*64 + j*16,
                                    acc[i][j], 128, wmma::mem_row_major);
    __syncthreads();

    // phase A: dist = ||b||^2 - 2*dot; per-row tile min
    {
        int rr = tid >> 1, h = tid & 1;
        float lmin = 3.0e38f;
        for (int j = h*64; j < h*64 + 64; j++) {
            float d = (n0 + j < NNPTS) ? (norms[j] - 2.0f * Cs[rr*128 + j]) : 3.0e38f;
            Cs[rr*128 + j] = d;
            lmin = fminf(lmin, d);
        }
        atomicMin(&tmin[rr], fenc(lmin));
    }
    __syncthreads();

    // phase B: append candidates within bound; publish tile min
    {
        int rr = tid >> 1, h = tid & 1;
        int gr = m0 + rr;
        float gb = fdec(g_minval[gr]);              // NaN when uninit; fminf ignores NaN
        float bound = fminf(fdec(tmin[rr]), gb) + EPS_SCREEN;
        for (int j = h*64; j < h*64 + 64; j++) {
            if (Cs[rr*128 + j] <= bound && (n0 + j) < NNPTS) {
                unsigned int pk = ((unsigned int)gr << 20) | (unsigned int)(n0 + j);
                int idx = atomicAdd(s_cnt, 1);
                if (idx < STAGE_CAP) stage[idx] = pk;
                else {
                    int gi = atomicAdd(&g_cand_cnt, 1);
                    if (gi < CAND_CAP) g_cands[gi] = pk;
                }
            }
        }
        if (h == 0) atomicMin(&g_minval[gr], tmin[rr]);
    }
    __syncthreads();
    if (tid == 0) {
        int c = *s_cnt; if (c > STAGE_CAP) c = STAGE_CAP;
        *s_cnt = c;
        *s_base = atomicAdd(&g_cand_cnt, c);
    }
    __syncthreads();
    {
        int c = *s_cnt, base = *s_base;
        for (int k = tid; k < c; k += 256) {
            int gi = base + k;
            if (gi < CAND_CAP) g_cands[gi] = stage[k];
        }
    }
}

// ---------------- pass 2: exact fp32 re-rank of candidates ------------------
__global__ void k_pass2(const float* __restrict__ codes, const float* __restrict__ cb) {
    int cnt = g_cand_cnt; if (cnt > CAND_CAP) cnt = CAND_CAP;
    int lane = threadIdx.x & 31;
    int warp = (blockIdx.x * blockDim.x + threadIdx.x) >> 5;
    int nwarp = (gridDim.x * blockDim.x) >> 5;
    for (int i = warp; i < cnt; i += nwarp) {
        unsigned int pk = g_cands[i];
        int row = pk >> 20;
        int j   = pk & 0xFFFFF;
        const float4* c4 = (const float4*)(codes + (size_t)row * CC) + lane * 2;
        const float4* b4 = (const float4*)(cb    + (size_t)j   * CC) + lane * 2;
        float4 c0 = c4[0], c1 = c4[1], b0 = b4[0], b1 = b4[1];
        float dx, s;
        dx = c0.x-b0.x; s  = dx*dx; dx = c0.y-b0.y; s += dx*dx;
        dx = c0.z-b0.z; s += dx*dx; dx = c0.w-b0.w; s += dx*dx;
        dx = c1.x-b1.x; s += dx*dx; dx = c1.y-b1.y; s += dx*dx;
        dx = c1.z-b1.z; s += dx*dx; dx = c1.w-b1.w; s += dx*dx;
        #pragma unroll
        for (int o = 16; o; o >>= 1) s += __shfl_xor_sync(0xFFFFFFFFu, s, o);
        if (lane == 0) {
            unsigned long long p =
                ((unsigned long long)__float_as_uint(s) << 20) | (unsigned int)j;
            atomicMin(&g_exact[row], p);
        }
    }
}

// ---------------- gather: prev = codebook[argmin] ----------------------------
__global__ void k_gather(const float* __restrict__ cb) {
    int row = blockIdx.x;
    int j = (int)(g_exact[row] & 0xFFFFFull);
    float4 v = ((const float4*)(cb + (size_t)j * CC))[threadIdx.x];
    ((float4*)(g_scratch + (size_t)row * CC))[threadIdx.x] = v;
}

// ---------------- MLP GEMM: out = [tanh](x(+xadd) @ W^T + b), bf16x3 --------
template<bool TANH, bool ADDOUT>
__global__ void k_gemm(const float* __restrict__ x, const float* __restrict__ xadd,
                       const float* __restrict__ w, const float* __restrict__ bias,
                       float* __restrict__ out, int Kd, int Nd) {
    __shared__ __nv_bfloat16 Ah[64*32], Al[64*32], Bh[64*32], Bl[64*32];
    __shared__ float Cs[64*64];
    int tid = threadIdx.x;
    int m0 = blockIdx.y * 64, n0 = blockIdx.x * 64;
    int wid = tid >> 5, wm = wid >> 1, wn = wid & 1;   // 2x2 warps, 32x32 each

    wmma::fragment<wmma::accumulator,16,16,16,float> acc[2][2];
    #pragma unroll
    for (int i = 0; i < 2; i++)
        #pragma unroll
        for (int j = 0; j < 2; j++) wmma::fill_fragment(acc[i][j], 0.0f);

    int r = tid >> 1, q = tid & 1;

    for (int kc = 0; kc < Kd; kc += 32) {
        __syncthreads();
        {
            const float* ap = x + (size_t)(m0 + r) * Kd + kc + q * 16;
            float v[16];
            *(float4*)(v+0)  = *(const float4*)(ap + 0);
            *(float4*)(v+4)  = *(const float4*)(ap + 4);
            *(float4*)(v+8)  = *(const float4*)(ap + 8);
            *(float4*)(v+12) = *(const float4*)(ap + 12);
            if (xadd) {
                const float* xp = xadd + (size_t)(m0 + r) * Kd + kc + q * 16;
                #pragma unroll
                for (int i = 0; i < 16; i += 4) {
                    float4 t = *(const float4*)(xp + i);
                    v[i+0]+=t.x; v[i+1]+=t.y; v[i+2]+=t.z; v[i+3]+=t.w;
                }
            }
            split8(Ah + r*32 + q*16,     Al + r*32 + q*16,     v);
            split8(Ah + r*32 + q*16 + 8, Al + r*32 + q*16 + 8, v + 8);
        }
        {
            const float* bp = w + (size_t)(n0 + r) * Kd + kc + q * 16;
            float v[16];
            *(float4*)(v+0)  = *(const float4*)(bp + 0);
            *(float4*)(v+4)  = *(const float4*)(bp + 4);
            *(float4*)(v+8)  = *(const float4*)(bp + 8);
            *(float4*)(v+12) = *(const float4*)(bp + 12);
            split8(Bh + r*32 + q*16,     Bl + r*32 + q*16,     v);
            split8(Bh + r*32 + q*16 + 8, Bl + r*32 + q*16 + 8, v + 8);
        }
        __syncthreads();
        #pragma unroll
        for (int kk = 0; kk < 32; kk += 16) {
            wmma::fragment<wmma::matrix_a,16,16,16,__nv_bfloat16,wmma::row_major> fah[2], fal[2];
            wmma::fragment<wmma::matrix_b,16,16,16,__nv_bfloat16,wmma::col_major> fbh[2], fbl[2];
            #pragma unroll
            for (int i = 0; i < 2; i++) {
                wmma::load_matrix_sync(fah[i], Ah + (wm*32 + i*16)*32 + kk, 32);
                wmma::load_matrix_sync(fal[i], Al + (wm*32 + i*16)*32 + kk, 32);
            }
            #pragma unroll
            for (int j = 0; j < 2; j++) {
                wmma::load_matrix_sync(fbh[j], Bh + (wn*32 + j*16)*32 + kk, 32);
                wmma::load_matrix_sync(fbl[j], Bl + (wn*32 + j*16)*32 + kk, 32);
            }
            #pragma unroll
            for (int i = 0; i < 2; i++)
                #pragma unroll
                for (int j = 0; j < 2; j++) {
                    wmma::mma_sync(acc[i][j], fah[i], fbh[j], acc[i][j]);
                    wmma::mma_sync(acc[i][j], fah[i], fbl[j], acc[i][j]);
                    wmma::mma_sync(acc[i][j], fal[i], fbh[j], acc[i][j]);
                }
        }
    }
    __syncthreads();
    #pragma unroll
    for (int i = 0; i < 2; i++)
        #pragma unroll
        for (int j = 0; j < 2; j++)
            wmma::store_matrix_sync(Cs + (wm*32 + i*16)*64 + wn*32 + j*16,
                                    acc[i][j], 64, wmma::mem_row_major);
    __syncthreads();
    for (int idx = tid; idx < 64*64; idx += 128) {
        int rr = idx >> 6, cc = idx & 63;
        float v = Cs[idx] + bias[n0 + cc];
        if (TANH) v = tanhf(v);
        float* o = out + (size_t)(m0 + rr) * Nd + n0 + cc;
        if (ADDOUT) *o += v; else *o = v;
    }
}

// ---------------- host ------------------------------------------------------
extern "C" void kernel_launch(void* const* d_in, const int* in_sizes, int n_in,
                              void* d_out, int out_size) {
    const float* codes = (const float*)d_in[0];
    const float* cb    = (const float*)d_in[1];
    const float *w_in=(const float*)d_in[2],  *b_in=(const float*)d_in[3];
    const float *w_h1=(const float*)d_in[4],  *b_h1=(const float*)d_in[5];
    const float *w_s2=(const float*)d_in[6],  *b_s2=(const float*)d_in[7];
    const float *w_s3=(const float*)d_in[8],  *b_s3=(const float*)d_in[9];
    const float *w_h2=(const float*)d_in[10], *b_h2=(const float*)d_in[11];
    const float *w_s1o=(const float*)d_in[12],*b_s1o=(const float*)d_in[13];
    const float *w_s2o=(const float*)d_in[14],*b_s2o=(const float*)d_in[15];
    const float *w_h3=(const float*)d_in[16], *b_h3=(const float*)d_in[17];
    const float *w_mu=(const float*)d_in[18], *b_mu=(const float*)d_in[19];
    const float *w_s =(const float*)d_in[20], *b_s =(const float*)d_in[21];

    float* mu = (float*)d_out;
    float* ls = mu + BB*CC;

    float* S = nullptr;
    cudaGetSymbolAddress((void**)&S, g_scratch);
    float* prev = S;
    float* bi   = S + BB*CC;
    float* h1   = bi + BB*HH;
    float* s2   = h1 + BB*HH;
    float* s3   = s2 + BB*HH;
    float* h2   = s3 + BB*HH;
    float* ob   = h2 + BB*HH;

    cudaFuncSetAttribute(k_pass1, cudaFuncAttributeMaxDynamicSharedMemorySize, P1_SMEM);

    k_init<<<2, 256>>>();
    k_pass1<<<dim3(4, (NNPTS + 127) / 128), 256, P1_SMEM>>>(codes, cb);
    k_pass2<<<1024, 256>>>(codes, cb);
    k_gather<<<BB, 64>>>(cb);

    dim3 blk(128);
    dim3 gH(HH/64, BB/64);   // 16 x 8
    dim3 gC(CC/64, BB/64);   // 4 x 8
    k_gemm<true,false><<<gH, blk>>>(prev, nullptr, w_in,  b_in,  bi, CC, HH);
    k_gemm<true,false><<<gH, blk>>>(bi,   nullptr, w_h1,  b_h1,  h1, HH, HH);
    k_gemm<true,false><<<gH, blk>>>(h1,   nullptr, w_s2,  b_s2,  s2, HH, HH);
    k_gemm<true,false><<<gH, blk>>>(h1,   nullptr, w_s3,  b_s3,  s3, HH, HH);
    k_gemm<true,false><<<gH, blk>>>(h1,   s2,      w_h2,  b_h2,  h2, HH, HH);
    k_gemm<true,false><<<gH, blk>>>(h1,   nullptr, w_s1o, b_s1o, ob, HH, HH);
    k_gemm<true,true ><<<gH, blk>>>(h2,   nullptr, w_s2o, b_s2o, ob, HH, HH);
    k_gemm<true,true ><<<gH, blk>>>(h2,   s3,      w_h3,  b_h3,  ob, HH, HH);
    k_gemm<false,false><<<gC, blk>>>(ob,  nullptr, w_mu,  b_mu,  mu, HH, CC);
    k_gemm<false,false><<<gC, blk>>>(ob,  nullptr, w_s,   b_s,   ls, HH, CC);
}

// round 4
// speedup vs baseline: 2.5421x; 2.5421x over previous
#include <cuda_runtime.h>
#include <cuda_bf16.h>
#include <mma.h>
#include <cstdint>
#include <cstddef>

using namespace nvcuda;

#define BB 512
#define CC 256
#define NNPTS 500000
#define HH 1024
#define CAND_CAP (8*1024*1024)
#define STAGE_CAP 4096
#define EPS_SCREEN 3.0f

// ---------------- static device scratch -------------------------------------
__device__ unsigned int        g_minval[BB];
__device__ unsigned long long  g_exact[BB];
__device__ unsigned int        g_cands[CAND_CAP];
__device__ int                 g_cand_cnt;
__device__ float               g_scratch[BB*CC + 8*BB*HH];
__device__ __nv_bfloat16       g_codesbf[BB*CC];

// ---------------- helpers ----------------------------------------------------
__device__ __forceinline__ unsigned int fenc(float f) {
    unsigned int b = __float_as_uint(f);
    return (b & 0x80000000u) ? ~b : (b | 0x80000000u);
}
__device__ __forceinline__ float fdec(unsigned int u) {
    unsigned int b = (u & 0x80000000u) ? (u & 0x7FFFFFFFu) : ~u;
    return __uint_as_float(b);
}
// pack 8 fp32 -> 8 bf16 (16B) single store
__device__ __forceinline__ void pack8(void* dst, const float* v) {
    __nv_bfloat162 h[4];
    h[0] = __floats2bfloat162_rn(v[0], v[1]);
    h[1] = __floats2bfloat162_rn(v[2], v[3]);
    h[2] = __floats2bfloat162_rn(v[4], v[5]);
    h[3] = __floats2bfloat162_rn(v[6], v[7]);
    *(uint4*)dst = *(uint4*)h;
}
// split 8 fp32 into hi/lo bf16, packed 16B stores
__device__ __forceinline__ void split_pack8(void* hdst, void* ldst, const float* v) {
    float lo[8];
    __nv_bfloat16 hb[8];
    #pragma unroll
    for (int i = 0; i < 8; i++) {
        hb[i] = __float2bfloat16(v[i]);
        lo[i] = v[i] - __bfloat162float(hb[i]);
    }
    *(uint4*)hdst = *(uint4*)hb;
    pack8(ldst, lo);
}

// ---------------- init + prep ------------------------------------------------
__global__ void k_init() {
    int t = blockIdx.x * blockDim.x + threadIdx.x;
    if (t < BB) {
        g_minval[t] = 0xFFFFFFFFu;
        g_exact[t]  = 0xFFFFFFFFFFFFFFFFull;
    }
    if (t == 0) g_cand_cnt = 0;
}
__global__ void k_prep(const float* __restrict__ codes) {
    int i = blockIdx.x * blockDim.x + threadIdx.x;   // one per 8 elems
    float v[8];
    *(float4*)(v+0) = ((const float4*)codes)[i*2+0];
    *(float4*)(v+4) = ((const float4*)codes)[i*2+1];
    pack8(((uint4*)g_codesbf) + i, v);
}

// ---------------- pass 1: pipelined bf16 WMMA screen -------------------------
// smem byte layout:
//   Cs    : f32 [128 x 132]           0      .. 67584
//   norms : f32 [128]                 67584  .. 68096
//   tmin  : u32 [128]                 68096  .. 68608
//   stage : u32 [4096]                68608  .. 84992
//   As    : bf16[128 x 264]           84992  .. 152576
//   Bs    : bf16[128 x 72]            152576 .. 171008
//   cnt   : 2 x int                   171008 .. 171016
#define P1_SMEM 171040
#define AS_LD 264
#define BS_LD 72
#define CS_LD 132

__global__ void __launch_bounds__(256,1)
k_pass1(const float* __restrict__ cb) {
    extern __shared__ __align__(16) char smem[];
    float*         Cs    = (float*)smem;
    float*         norms = (float*)(smem + 67584);
    unsigned int*  tmin  = (unsigned int*)(smem + 68096);
    unsigned int*  stage = (unsigned int*)(smem + 68608);
    __nv_bfloat16* As    = (__nv_bfloat16*)(smem + 84992);
    __nv_bfloat16* Bs    = (__nv_bfloat16*)(smem + 152576);
    int*           s_cnt = (int*)(smem + 171008);
    int*           s_base= s_cnt + 1;

    int tid = threadIdx.x;
    int m0 = blockIdx.x * 128;
    int n0 = blockIdx.y * 128;

    if (tid < 128) { norms[tid] = 0.0f; tmin[tid] = 0xFFFFFFFFu; }
    if (tid == 0)  { *s_cnt = 0; }

    // ---- load A (bf16 codes) once, full K ----
    #pragma unroll
    for (int c = 0; c < 16; c++) {
        int i = tid + 256 * c;
        int row = i >> 5, col = (i & 31) * 8;
        uint4 v = *(const uint4*)(g_codesbf + (size_t)(m0 + row) * CC + col);
        *(uint4*)(As + row * AS_LD + col) = v;
    }

    // ---- B prefetch state: 4 chunks of 8 floats per thread per k-step ----
    int brow0 = tid >> 3;                 // + 32*c
    int bcol  = (tid & 7) * 8;            // within 64-col k-step
    float vb[4][8];
    float nrm[4] = {0.f, 0.f, 0.f, 0.f};

    auto load_b = [&](int ks) {
        #pragma unroll
        for (int c = 0; c < 4; c++) {
            int row = brow0 + 32 * c;
            int gj = n0 + row;
            if (gj < NNPTS) {
                const float* p = cb + (size_t)gj * CC + ks * 64 + bcol;
                *(float4*)(vb[c] + 0) = *(const float4*)(p + 0);
                *(float4*)(vb[c] + 4) = *(const float4*)(p + 4);
                float s = 0.f;
                #pragma unroll
                for (int e = 0; e < 8; e++) s += vb[c][e] * vb[c][e];
                nrm[c] += s;
            } else {
                #pragma unroll
                for (int e = 0; e < 8; e++) vb[c][e] = 0.f;
            }
        }
    };
    load_b(0);

    int wid = tid >> 5;
    int wm  = wid >> 1;   // 0..3
    int wn  = wid & 1;    // 0..1
    wmma::fragment<wmma::accumulator,16,16,16,float> acc[2][4];
    #pragma unroll
    for (int i = 0; i < 2; i++)
        #pragma unroll
        for (int j = 0; j < 4; j++) wmma::fill_fragment(acc[i][j], 0.0f);

    __syncthreads();

    // ---- mainloop: 4 k-steps of 64, reg-prefetch overlapping MMA ----
    #pragma unroll
    for (int ks = 0; ks < 4; ks++) {
        #pragma unroll
        for (int c = 0; c < 4; c++)
            pack8(Bs + (brow0 + 32 * c) * BS_LD + bcol, vb[c]);
        __syncthreads();
        if (ks < 3) load_b(ks + 1);       // LDG overlaps MMA below
        #pragma unroll
        for (int kk = 0; kk < 64; kk += 16) {
            wmma::fragment<wmma::matrix_a,16,16,16,__nv_bfloat16,wmma::row_major> fa[2];
            wmma::fragment<wmma::matrix_b,16,16,16,__nv_bfloat16,wmma::col_major> fb[4];
            #pragma unroll
            for (int i = 0; i < 2; i++)
                wmma::load_matrix_sync(fa[i], As + (wm*32 + i*16)*AS_LD + ks*64 + kk, AS_LD);
            #pragma unroll
            for (int j = 0; j < 4; j++)
                wmma::load_matrix_sync(fb[j], Bs + (wn*64 + j*16)*BS_LD + kk, BS_LD);
            #pragma unroll
            for (int i = 0; i < 2; i++)
                #pragma unroll
                for (int j = 0; j < 4; j++)
                    wmma::mma_sync(acc[i][j], fa[i], fb[j], acc[i][j]);
        }
        __syncthreads();
    }

    // ---- norms + C store ----
    #pragma unroll
    for (int c = 0; c < 4; c++) atomicAdd(&norms[brow0 + 32 * c], nrm[c]);
    #pragma unroll
    for (int i = 0; i < 2; i++)
        #pragma unroll
        for (int j = 0; j < 4; j++)
            wmma::store_matrix_sync(Cs + (wm*32 + i*16)*CS_LD + wn*64 + j*16,
                                    acc[i][j], CS_LD, wmma::mem_row_major);
    __syncthreads();

    // ---- phase A: dist = ||b||^2 - 2*dot ; per-row tile min ----
    {
        int rr = tid >> 1, h = tid & 1;
        float lmin = 3.0e38f;
        for (int j = h*64; j < h*64 + 64; j++) {
            float d = (n0 + j < NNPTS) ? (norms[j] - 2.0f * Cs[rr*CS_LD + j]) : 3.0e38f;
            Cs[rr*CS_LD + j] = d;
            lmin = fminf(lmin, d);
        }
        atomicMin(&tmin[rr], fenc(lmin));
    }
    __syncthreads();

    // ---- phase B: candidates within bound ----
    {
        int rr = tid >> 1, h = tid & 1;
        int gr = m0 + rr;
        float gb = fdec(g_minval[gr]);                 // NaN when uninit; fminf ignores NaN
        float bound = fminf(fdec(tmin[rr]), gb) + EPS_SCREEN;
        for (int j = h*64; j < h*64 + 64; j++) {
            if (Cs[rr*CS_LD + j] <= bound && (n0 + j) < NNPTS) {
                unsigned int pk = ((unsigned int)gr << 20) | (unsigned int)(n0 + j);
                int idx = atomicAdd(s_cnt, 1);
                if (idx < STAGE_CAP) stage[idx] = pk;
                else {
                    int gi = atomicAdd(&g_cand_cnt, 1);
                    if (gi < CAND_CAP) g_cands[gi] = pk;
                }
            }
        }
        if (h == 0) atomicMin(&g_minval[gr], tmin[rr]);
    }
    __syncthreads();
    if (tid == 0) {
        int c = *s_cnt; if (c > STAGE_CAP) c = STAGE_CAP;
        *s_cnt = c;
        *s_base = atomicAdd(&g_cand_cnt, c);
    }
    __syncthreads();
    {
        int c = *s_cnt, base = *s_base;
        for (int k = tid; k < c; k += 256) {
            int gi = base + k;
            if (gi < CAND_CAP) g_cands[gi] = stage[k];
        }
    }
}

// ---------------- pass 2: exact fp32 re-rank ---------------------------------
__global__ void k_pass2(const float* __restrict__ codes, const float* __restrict__ cb) {
    int cnt = g_cand_cnt; if (cnt > CAND_CAP) cnt = CAND_CAP;
    int lane = threadIdx.x & 31;
    int warp = (blockIdx.x * blockDim.x + threadIdx.x) >> 5;
    int nwarp = (gridDim.x * blockDim.x) >> 5;
    for (int i = warp; i < cnt; i += nwarp) {
        unsigned int pk = g_cands[i];
        int row = pk >> 20;
        int j   = pk & 0xFFFFF;
        const float4* c4 = (const float4*)(codes + (size_t)row * CC) + lane * 2;
        const float4* b4 = (const float4*)(cb    + (size_t)j   * CC) + lane * 2;
        float4 c0 = c4[0], c1 = c4[1], b0 = b4[0], b1 = b4[1];
        float dx, s;
        dx = c0.x-b0.x; s  = dx*dx; dx = c0.y-b0.y; s += dx*dx;
        dx = c0.z-b0.z; s += dx*dx; dx = c0.w-b0.w; s += dx*dx;
        dx = c1.x-b1.x; s += dx*dx; dx = c1.y-b1.y; s += dx*dx;
        dx = c1.z-b1.z; s += dx*dx; dx = c1.w-b1.w; s += dx*dx;
        #pragma unroll
        for (int o = 16; o; o >>= 1) s += __shfl_xor_sync(0xFFFFFFFFu, s, o);
        if (lane == 0) {
            unsigned long long p =
                ((unsigned long long)__float_as_uint(s) << 20) | (unsigned int)j;
            atomicMin(&g_exact[row], p);
        }
    }
}

// ---------------- gather ------------------------------------------------------
__global__ void k_gather(const float* __restrict__ cb) {
    int row = blockIdx.x;
    int j = (int)(g_exact[row] & 0xFFFFFull);
    float4 v = ((const float4*)(cb + (size_t)j * CC))[threadIdx.x];
    ((float4*)(g_scratch + (size_t)row * CC))[threadIdx.x] = v;
}

// ---------------- MLP GEMM: out = [tanh](x(+xadd) @ W^T + b), bf16x3 ----------
#define G_LD 40
#define GC_LD 68
template<bool TANH, bool ADDOUT>
__global__ void __launch_bounds__(128)
k_gemm(const float* __restrict__ x, const float* __restrict__ xadd,
       const float* __restrict__ w, const float* __restrict__ bias,
       float* __restrict__ out, int Kd, int Nd) {
    __shared__ __nv_bfloat16 Ah[64*G_LD], Al[64*G_LD], Bh[64*G_LD], Bl[64*G_LD];
    __shared__ float Cs[64*GC_LD];
    int tid = threadIdx.x;
    int m0 = blockIdx.y * 64, n0 = blockIdx.x * 64;
    int wid = tid >> 5, wm = wid >> 1, wn = wid & 1;
    int r = tid >> 1, q = tid & 1;

    float va[16], vbv[16];
    auto load_ab = [&](int kc) {
        const float* ap = x + (size_t)(m0 + r) * Kd + kc + q * 16;
        *(float4*)(va+0)  = *(const float4*)(ap + 0);
        *(float4*)(va+4)  = *(const float4*)(ap + 4);
        *(float4*)(va+8)  = *(const float4*)(ap + 8);
        *(float4*)(va+12) = *(const float4*)(ap + 12);
        if (xadd) {
            const float* xp = xadd + (size_t)(m0 + r) * Kd + kc + q * 16;
            #pragma unroll
            for (int i = 0; i < 16; i += 4) {
                float4 t = *(const float4*)(xp + i);
                va[i+0]+=t.x; va[i+1]+=t.y; va[i+2]+=t.z; va[i+3]+=t.w;
            }
        }
        const float* bp = w + (size_t)(n0 + r) * Kd + kc + q * 16;
        *(float4*)(vbv+0)  = *(const float4*)(bp + 0);
        *(float4*)(vbv+4)  = *(const float4*)(bp + 4);
        *(float4*)(vbv+8)  = *(const float4*)(bp + 8);
        *(float4*)(vbv+12) = *(const float4*)(bp + 12);
    };
    load_ab(0);

    wmma::fragment<wmma::accumulator,16,16,16,float> acc[2][2];
    #pragma unroll
    for (int i = 0; i < 2; i++)
        #pragma unroll
        for (int j = 0; j < 2; j++) wmma::fill_fragment(acc[i][j], 0.0f);

    for (int kc = 0; kc < Kd; kc += 32) {
        split_pack8(Ah + r*G_LD + q*16,     Al + r*G_LD + q*16,     va);
        split_pack8(Ah + r*G_LD + q*16 + 8, Al + r*G_LD + q*16 + 8, va + 8);
        split_pack8(Bh + r*G_LD + q*16,     Bl + r*G_LD + q*16,     vbv);
        split_pack8(Bh + r*G_LD + q*16 + 8, Bl + r*G_LD + q*16 + 8, vbv + 8);
        __syncthreads();
        if (kc + 32 < Kd) load_ab(kc + 32);     // LDG overlaps MMA
        #pragma unroll
        for (int kk = 0; kk < 32; kk += 16) {
            wmma::fragment<wmma::matrix_a,16,16,16,__nv_bfloat16,wmma::row_major> fah[2], fal[2];
            wmma::fragment<wmma::matrix_b,16,16,16,__nv_bfloat16,wmma::col_major> fbh[2], fbl[2];
            #pragma unroll
            for (int i = 0; i < 2; i++) {
                wmma::load_matrix_sync(fah[i], Ah + (wm*32 + i*16)*G_LD + kk, G_LD);
                wmma::load_matrix_sync(fal[i], Al + (wm*32 + i*16)*G_LD + kk, G_LD);
            }
            #pragma unroll
            for (int j = 0; j < 2; j++) {
                wmma::load_matrix_sync(fbh[j], Bh + (wn*32 + j*16)*G_LD + kk, G_LD);
                wmma::load_matrix_sync(fbl[j], Bl + (wn*32 + j*16)*G_LD + kk, G_LD);
            }
            #pragma unroll
            for (int i = 0; i < 2; i++)
                #pragma unroll
                for (int j = 0; j < 2; j++) {
                    wmma::mma_sync(acc[i][j], fah[i], fbh[j], acc[i][j]);
                    wmma::mma_sync(acc[i][j], fah[i], fbl[j], acc[i][j]);
                    wmma::mma_sync(acc[i][j], fal[i], fbh[j], acc[i][j]);
                }
        }
        __syncthreads();
    }
    #pragma unroll
    for (int i = 0; i < 2; i++)
        #pragma unroll
        for (int j = 0; j < 2; j++)
            wmma::store_matrix_sync(Cs + (wm*32 + i*16)*GC_LD + wn*32 + j*16,
                                    acc[i][j], GC_LD, wmma::mem_row_major);
    __syncthreads();
    for (int idx = tid; idx < 64*64; idx += 128) {
        int rr = idx >> 6, cc = idx & 63;
        float v = Cs[rr*GC_LD + cc] + bias[n0 + cc];
        if (TANH) v = tanhf(v);
        float* o = out + (size_t)(m0 + rr) * Nd + n0 + cc;
        if (ADDOUT) *o += v; else *o = v;
    }
}

// ---------------- host ---------------------------------------------------------
extern "C" void kernel_launch(void* const* d_in, const int* in_sizes, int n_in,
                              void* d_out, int out_size) {
    const float* codes = (const float*)d_in[0];
    const float* cb    = (const float*)d_in[1];
    const float *w_in=(const float*)d_in[2],  *b_in=(const float*)d_in[3];
    const float *w_h1=(const float*)d_in[4],  *b_h1=(const float*)d_in[5];
    const float *w_s2=(const float*)d_in[6],  *b_s2=(const float*)d_in[7];
    const float *w_s3=(const float*)d_in[8],  *b_s3=(const float*)d_in[9];
    const float *w_h2=(const float*)d_in[10], *b_h2=(const float*)d_in[11];
    const float *w_s1o=(const float*)d_in[12],*b_s1o=(const float*)d_in[13];
    const float *w_s2o=(const float*)d_in[14],*b_s2o=(const float*)d_in[15];
    const float *w_h3=(const float*)d_in[16], *b_h3=(const float*)d_in[17];
    const float *w_mu=(const float*)d_in[18], *b_mu=(const float*)d_in[19];
    const float *w_s =(const float*)d_in[20], *b_s =(const float*)d_in[21];

    float* mu = (float*)d_out;
    float* ls = mu + BB*CC;

    float* S = nullptr;
    cudaGetSymbolAddress((void**)&S, g_scratch);
    float* prev = S;
    float* bi   = S + BB*CC;
    float* h1   = bi + BB*HH;
    float* s2   = h1 + BB*HH;
    float* s3   = s2 + BB*HH;
    float* h2   = s3 + BB*HH;
    float* ob   = h2 + BB*HH;

    cudaFuncSetAttribute(k_pass1, cudaFuncAttributeMaxDynamicSharedMemorySize, P1_SMEM);

    k_init<<<2, 256>>>();
    k_prep<<<64, 256>>>(codes);
    k_pass1<<<dim3(4, (NNPTS + 127) / 128), 256, P1_SMEM>>>(cb);
    k_pass2<<<1024, 256>>>(codes, cb);
    k_gather<<<BB, 64>>>(cb);

    dim3 blk(128);
    dim3 gH(HH/64, BB/64);   // 16 x 8
    dim3 gC(CC/64, BB/64);   // 4 x 8
    k_gemm<true,false><<<gH, blk>>>(prev, nullptr, w_in,  b_in,  bi, CC, HH);
    k_gemm<true,false><<<gH, blk>>>(bi,   nullptr, w_h1,  b_h1,  h1, HH, HH);
    k_gemm<true,false><<<gH, blk>>>(h1,   nullptr, w_s2,  b_s2,  s2, HH, HH);
    k_gemm<true,false><<<gH, blk>>>(h1,   nullptr, w_s3,  b_s3,  s3, HH, HH);
    k_gemm<true,false><<<gH, blk>>>(h1,   s2,      w_h2,  b_h2,  h2, HH, HH);
    k_gemm<true,false><<<gH, blk>>>(h1,   nullptr, w_s1o, b_s1o, ob, HH, HH);
    k_gemm<true,true ><<<gH, blk>>>(h2,   nullptr, w_s2o, b_s2o, ob, HH, HH);
    k_gemm<true,true ><<<gH, blk>>>(h2,   s3,      w_h3,  b_h3,  ob, HH, HH);
    k_gemm<false,false><<<gC, blk>>>(ob,  nullptr, w_mu,  b_mu,  mu, HH, CC);
    k_gemm<false,false><<<gC, blk>>>(ob,  nullptr, w_s,   b_s,   ls, HH, CC);
}

// round 5
// speedup vs baseline: 2.5423x; 1.0001x over previous
#include <cuda_runtime.h>
#include <cuda_bf16.h>
#include <mma.h>
#include <cstdint>
#include <cstddef>

using namespace nvcuda;

#define BB 512
#define CC 256
#define NNPTS 500000
#define HH 1024
#define CAND_CAP (8*1024*1024)
#define STAGE_CAP 4096
#define EPS_SCREEN 3.0f

// ---------------- static device scratch -------------------------------------
__device__ unsigned int        g_minval[BB];
__device__ unsigned long long  g_exact[BB];
__device__ unsigned int        g_cands[CAND_CAP];
__device__ int                 g_cand_cnt;
__device__ float               g_scratch[BB*CC + 8*BB*HH];
__device__ __nv_bfloat16       g_codesbf[BB*CC];

// ---------------- helpers ----------------------------------------------------
__device__ __forceinline__ unsigned int fenc(float f) {
    unsigned int b = __float_as_uint(f);
    return (b & 0x80000000u) ? ~b : (b | 0x80000000u);
}
__device__ __forceinline__ float fdec(unsigned int u) {
    unsigned int b = (u & 0x80000000u) ? (u & 0x7FFFFFFFu) : ~u;
    return __uint_as_float(b);
}
// pack 8 fp32 -> 8 bf16 (16B) single store
__device__ __forceinline__ void pack8(void* dst, const float* v) {
    __nv_bfloat162 h[4];
    h[0] = __floats2bfloat162_rn(v[0], v[1]);
    h[1] = __floats2bfloat162_rn(v[2], v[3]);
    h[2] = __floats2bfloat162_rn(v[4], v[5]);
    h[3] = __floats2bfloat162_rn(v[6], v[7]);
    *(uint4*)dst = *(uint4*)h;
}
// split 8 fp32 into hi/lo bf16, packed 16B stores
__device__ __forceinline__ void split_pack8(void* hdst, void* ldst, const float* v) {
    float lo[8];
    __nv_bfloat16 hb[8];
    #pragma unroll
    for (int i = 0; i < 8; i++) {
        hb[i] = __float2bfloat16(v[i]);
        lo[i] = v[i] - __bfloat162float(hb[i]);
    }
    *(uint4*)hdst = *(uint4*)hb;
    pack8(ldst, lo);
}

// ---------------- init + prep ------------------------------------------------
__global__ void k_init() {
    int t = blockIdx.x * blockDim.x + threadIdx.x;
    if (t < BB) {
        g_minval[t] = 0xFFFFFFFFu;
        g_exact[t]  = 0xFFFFFFFFFFFFFFFFull;
    }
    if (t == 0) g_cand_cnt = 0;
}
__global__ void k_prep(const float* __restrict__ codes) {
    int i = blockIdx.x * blockDim.x + threadIdx.x;   // one per 8 elems
    float v[8];
    *(float4*)(v+0) = ((const float4*)codes)[i*2+0];
    *(float4*)(v+4) = ((const float4*)codes)[i*2+1];
    pack8(((uint4*)g_codesbf) + i, v);
}

// ---------------- pass 1: pipelined bf16 WMMA screen -------------------------
// smem byte layout:
//   Cs    : f32 [128 x 132]           0      .. 67584
//   norms : f32 [128]                 67584  .. 68096
//   tmin  : u32 [128]                 68096  .. 68608
//   stage : u32 [4096]                68608  .. 84992
//   As    : bf16[128 x 264]           84992  .. 152576
//   Bs    : bf16[128 x 72]            152576 .. 171008
//   cnt   : 2 x int                   171008 .. 171016
#define P1_SMEM 171040
#define AS_LD 264
#define BS_LD 72
#define CS_LD 132

__global__ void __launch_bounds__(256,1)
k_pass1(const float* __restrict__ cb) {
    extern __shared__ __align__(16) char smem[];
    float*         Cs    = (float*)smem;
    float*         norms = (float*)(smem + 67584);
    unsigned int*  tmin  = (unsigned int*)(smem + 68096);
    unsigned int*  stage = (unsigned int*)(smem + 68608);
    __nv_bfloat16* As    = (__nv_bfloat16*)(smem + 84992);
    __nv_bfloat16* Bs    = (__nv_bfloat16*)(smem + 152576);
    int*           s_cnt = (int*)(smem + 171008);
    int*           s_base= s_cnt + 1;

    int tid = threadIdx.x;
    int m0 = blockIdx.x * 128;
    int n0 = blockIdx.y * 128;

    if (tid < 128) { norms[tid] = 0.0f; tmin[tid] = 0xFFFFFFFFu; }
    if (tid == 0)  { *s_cnt = 0; }

    // ---- load A (bf16 codes) once, full K ----
    #pragma unroll
    for (int c = 0; c < 16; c++) {
        int i = tid + 256 * c;
        int row = i >> 5, col = (i & 31) * 8;
        uint4 v = *(const uint4*)(g_codesbf + (size_t)(m0 + row) * CC + col);
        *(uint4*)(As + row * AS_LD + col) = v;
    }

    // ---- B prefetch state: 4 chunks of 8 floats per thread per k-step ----
    int brow0 = tid >> 3;                 // + 32*c
    int bcol  = (tid & 7) * 8;            // within 64-col k-step
    float vb[4][8];
    float nrm[4] = {0.f, 0.f, 0.f, 0.f};

    auto load_b = [&](int ks) {
        #pragma unroll
        for (int c = 0; c < 4; c++) {
            int row = brow0 + 32 * c;
            int gj = n0 + row;
            if (gj < NNPTS) {
                const float* p = cb + (size_t)gj * CC + ks * 64 + bcol;
                *(float4*)(vb[c] + 0) = *(const float4*)(p + 0);
                *(float4*)(vb[c] + 4) = *(const float4*)(p + 4);
                float s = 0.f;
                #pragma unroll
                for (int e = 0; e < 8; e++) s += vb[c][e] * vb[c][e];
                nrm[c] += s;
            } else {
                #pragma unroll
                for (int e = 0; e < 8; e++) vb[c][e] = 0.f;
            }
        }
    };
    load_b(0);

    int wid = tid >> 5;
    int wm  = wid >> 1;   // 0..3
    int wn  = wid & 1;    // 0..1
    wmma::fragment<wmma::accumulator,16,16,16,float> acc[2][4];
    #pragma unroll
    for (int i = 0; i < 2; i++)
        #pragma unroll
        for (int j = 0; j < 4; j++) wmma::fill_fragment(acc[i][j], 0.0f);

    __syncthreads();

    // ---- mainloop: 4 k-steps of 64, reg-prefetch overlapping MMA ----
    #pragma unroll
    for (int ks = 0; ks < 4; ks++) {
        #pragma unroll
        for (int c = 0; c < 4; c++)
            pack8(Bs + (brow0 + 32 * c) * BS_LD + bcol, vb[c]);
        __syncthreads();
        if (ks < 3) load_b(ks + 1);       // LDG overlaps MMA below
        #pragma unroll
        for (int kk = 0; kk < 64; kk += 16) {
            wmma::fragment<wmma::matrix_a,16,16,16,__nv_bfloat16,wmma::row_major> fa[2];
            wmma::fragment<wmma::matrix_b,16,16,16,__nv_bfloat16,wmma::col_major> fb[4];
            #pragma unroll
            for (int i = 0; i < 2; i++)
                wmma::load_matrix_sync(fa[i], As + (wm*32 + i*16)*AS_LD + ks*64 + kk, AS_LD);
            #pragma unroll
            for (int j = 0; j < 4; j++)
                wmma::load_matrix_sync(fb[j], Bs + (wn*64 + j*16)*BS_LD + kk, BS_LD);
            #pragma unroll
            for (int i = 0; i < 2; i++)
                #pragma unroll
                for (int j = 0; j < 4; j++)
                    wmma::mma_sync(acc[i][j], fa[i], fb[j], acc[i][j]);
        }
        __syncthreads();
    }

    // ---- norms + C store ----
    #pragma unroll
    for (int c = 0; c < 4; c++) atomicAdd(&norms[brow0 + 32 * c], nrm[c]);
    #pragma unroll
    for (int i = 0; i < 2; i++)
        #pragma unroll
        for (int j = 0; j < 4; j++)
            wmma::store_matrix_sync(Cs + (wm*32 + i*16)*CS_LD + wn*64 + j*16,
                                    acc[i][j], CS_LD, wmma::mem_row_major);
    __syncthreads();

    // ---- phase A: dist = ||b||^2 - 2*dot ; per-row tile min ----
    {
        int rr = tid >> 1, h = tid & 1;
        float lmin = 3.0e38f;
        for (int j = h*64; j < h*64 + 64; j++) {
            float d = (n0 + j < NNPTS) ? (norms[j] - 2.0f * Cs[rr*CS_LD + j]) : 3.0e38f;
            Cs[rr*CS_LD + j] = d;
            lmin = fminf(lmin, d);
        }
        atomicMin(&tmin[rr], fenc(lmin));
    }
    __syncthreads();

    // ---- phase B: candidates within bound ----
    {
        int rr = tid >> 1, h = tid & 1;
        int gr = m0 + rr;
        float gb = fdec(g_minval[gr]);                 // NaN when uninit; fminf ignores NaN
        float bound = fminf(fdec(tmin[rr]), gb) + EPS_SCREEN;
        for (int j = h*64; j < h*64 + 64; j++) {
            if (Cs[rr*CS_LD + j] <= bound && (n0 + j) < NNPTS) {
                unsigned int pk = ((unsigned int)gr << 20) | (unsigned int)(n0 + j);
                int idx = atomicAdd(s_cnt, 1);
                if (idx < STAGE_CAP) stage[idx] = pk;
                else {
                    int gi = atomicAdd(&g_cand_cnt, 1);
                    if (gi < CAND_CAP) g_cands[gi] = pk;
                }
            }
        }
        if (h == 0) atomicMin(&g_minval[gr], tmin[rr]);
    }
    __syncthreads();
    if (tid == 0) {
        int c = *s_cnt; if (c > STAGE_CAP) c = STAGE_CAP;
        *s_cnt = c;
        *s_base = atomicAdd(&g_cand_cnt, c);
    }
    __syncthreads();
    {
        int c = *s_cnt, base = *s_base;
        for (int k = tid; k < c; k += 256) {
            int gi = base + k;
            if (gi < CAND_CAP) g_cands[gi] = stage[k];
        }
    }
}

// ---------------- pass 2: exact fp32 re-rank ---------------------------------
__global__ void k_pass2(const float* __restrict__ codes, const float* __restrict__ cb) {
    int cnt = g_cand_cnt; if (cnt > CAND_CAP) cnt = CAND_CAP;
    int lane = threadIdx.x & 31;
    int warp = (blockIdx.x * blockDim.x + threadIdx.x) >> 5;
    int nwarp = (gridDim.x * blockDim.x) >> 5;
    for (int i = warp; i < cnt; i += nwarp) {
        unsigned int pk = g_cands[i];
        int row = pk >> 20;
        int j   = pk & 0xFFFFF;
        const float4* c4 = (const float4*)(codes + (size_t)row * CC) + lane * 2;
        const float4* b4 = (const float4*)(cb    + (size_t)j   * CC) + lane * 2;
        float4 c0 = c4[0], c1 = c4[1], b0 = b4[0], b1 = b4[1];
        float dx, s;
        dx = c0.x-b0.x; s  = dx*dx; dx = c0.y-b0.y; s += dx*dx;
        dx = c0.z-b0.z; s += dx*dx; dx = c0.w-b0.w; s += dx*dx;
        dx = c1.x-b1.x; s += dx*dx; dx = c1.y-b1.y; s += dx*dx;
        dx = c1.z-b1.z; s += dx*dx; dx = c1.w-b1.w; s += dx*dx;
        #pragma unroll
        for (int o = 16; o; o >>= 1) s += __shfl_xor_sync(0xFFFFFFFFu, s, o);
        if (lane == 0) {
            unsigned long long p =
                ((unsigned long long)__float_as_uint(s) << 20) | (unsigned int)j;
            atomicMin(&g_exact[row], p);
        }
    }
}

// ---------------- gather ------------------------------------------------------
__global__ void k_gather(const float* __restrict__ cb) {
    int row = blockIdx.x;
    int j = (int)(g_exact[row] & 0xFFFFFull);
    float4 v = ((const float4*)(cb + (size_t)j * CC))[threadIdx.x];
    ((float4*)(g_scratch + (size_t)row * CC))[threadIdx.x] = v;
}

// ---------------- MLP GEMM: out = [tanh](x(+xadd) @ W^T + b), bf16x3 ----------
#define G_LD 40
#define GC_LD 68
template<bool TANH, bool ADDOUT>
__global__ void __launch_bounds__(128)
k_gemm(const float* __restrict__ x, const float* __restrict__ xadd,
       const float* __restrict__ w, const float* __restrict__ bias,
       float* __restrict__ out, int Kd, int Nd) {
    __shared__ __nv_bfloat16 Ah[64*G_LD], Al[64*G_LD], Bh[64*G_LD], Bl[64*G_LD];
    __shared__ float Cs[64*GC_LD];
    int tid = threadIdx.x;
    int m0 = blockIdx.y * 64, n0 = blockIdx.x * 64;
    int wid = tid >> 5, wm = wid >> 1, wn = wid & 1;
    int r = tid >> 1, q = tid & 1;

    float va[16], vbv[16];
    auto load_ab = [&](int kc) {
        const float* ap = x + (size_t)(m0 + r) * Kd + kc + q * 16;
        *(float4*)(va+0)  = *(const float4*)(ap + 0);
        *(float4*)(va+4)  = *(const float4*)(ap + 4);
        *(float4*)(va+8)  = *(const float4*)(ap + 8);
        *(float4*)(va+12) = *(const float4*)(ap + 12);
        if (xadd) {
            const float* xp = xadd + (size_t)(m0 + r) * Kd + kc + q * 16;
            #pragma unroll
            for (int i = 0; i < 16; i += 4) {
                float4 t = *(const float4*)(xp + i);
                va[i+0]+=t.x; va[i+1]+=t.y; va[i+2]+=t.z; va[i+3]+=t.w;
            }
        }
        const float* bp = w + (size_t)(n0 + r) * Kd + kc + q * 16;
        *(float4*)(vbv+0)  = *(const float4*)(bp + 0);
        *(float4*)(vbv+4)  = *(const float4*)(bp + 4);
        *(float4*)(vbv+8)  = *(const float4*)(bp + 8);
        *(float4*)(vbv+12) = *(const float4*)(bp + 12);
    };
    load_ab(0);

    wmma::fragment<wmma::accumulator,16,16,16,float> acc[2][2];
    #pragma unroll
    for (int i = 0; i < 2; i++)
        #pragma unroll
        for (int j = 0; j < 2; j++) wmma::fill_fragment(acc[i][j], 0.0f);

    for (int kc = 0; kc < Kd; kc += 32) {
        split_pack8(Ah + r*G_LD + q*16,     Al + r*G_LD + q*16,     va);
        split_pack8(Ah + r*G_LD + q*16 + 8, Al + r*G_LD + q*16 + 8, va + 8);
        split_pack8(Bh + r*G_LD + q*16,     Bl + r*G_LD + q*16,     vbv);
        split_pack8(Bh + r*G_LD + q*16 + 8, Bl + r*G_LD + q*16 + 8, vbv + 8);
        __syncthreads();
        if (kc + 32 < Kd) load_ab(kc + 32);     // LDG overlaps MMA
        #pragma unroll
        for (int kk = 0; kk < 32; kk += 16) {
            wmma::fragment<wmma::matrix_a,16,16,16,__nv_bfloat16,wmma::row_major> fah[2], fal[2];
            wmma::fragment<wmma::matrix_b,16,16,16,__nv_bfloat16,wmma::col_major> fbh[2], fbl[2];
            #pragma unroll
            for (int i = 0; i < 2; i++) {
                wmma::load_matrix_sync(fah[i], Ah + (wm*32 + i*16)*G_LD + kk, G_LD);
                wmma::load_matrix_sync(fal[i], Al + (wm*32 + i*16)*G_LD + kk, G_LD);
            }
            #pragma unroll
            for (int j = 0; j < 2; j++) {
                wmma::load_matrix_sync(fbh[j], Bh + (wn*32 + j*16)*G_LD + kk, G_LD);
                wmma::load_matrix_sync(fbl[j], Bl + (wn*32 + j*16)*G_LD + kk, G_LD);
            }
            #pragma unroll
            for (int i = 0; i < 2; i++)
                #pragma unroll
                for (int j = 0; j < 2; j++) {
                    wmma::mma_sync(acc[i][j], fah[i], fbh[j], acc[i][j]);
                    wmma::mma_sync(acc[i][j], fah[i], fbl[j], acc[i][j]);
                    wmma::mma_sync(acc[i][j], fal[i], fbh[j], acc[i][j]);
                }
        }
        __syncthreads();
    }
    #pragma unroll
    for (int i = 0; i < 2; i++)
        #pragma unroll
        for (int j = 0; j < 2; j++)
            wmma::store_matrix_sync(Cs + (wm*32 + i*16)*GC_LD + wn*32 + j*16,
                                    acc[i][j], GC_LD, wmma::mem_row_major);
    __syncthreads();
    for (int idx = tid; idx < 64*64; idx += 128) {
        int rr = idx >> 6, cc = idx & 63;
        float v = Cs[rr*GC_LD + cc] + bias[n0 + cc];
        if (TANH) v = tanhf(v);
        float* o = out + (size_t)(m0 + rr) * Nd + n0 + cc;
        if (ADDOUT) *o += v; else *o = v;
    }
}

// ---------------- host ---------------------------------------------------------
extern "C" void kernel_launch(void* const* d_in, const int* in_sizes, int n_in,
                              void* d_out, int out_size) {
    const float* codes = (const float*)d_in[0];
    const float* cb    = (const float*)d_in[1];
    const float *w_in=(const float*)d_in[2],  *b_in=(const float*)d_in[3];
    const float *w_h1=(const float*)d_in[4],  *b_h1=(const float*)d_in[5];
    const float *w_s2=(const float*)d_in[6],  *b_s2=(const float*)d_in[7];
    const float *w_s3=(const float*)d_in[8],  *b_s3=(const float*)d_in[9];
    const float *w_h2=(const float*)d_in[10], *b_h2=(const float*)d_in[11];
    const float *w_s1o=(const float*)d_in[12],*b_s1o=(const float*)d_in[13];
    const float *w_s2o=(const float*)d_in[14],*b_s2o=(const float*)d_in[15];
    const float *w_h3=(const float*)d_in[16], *b_h3=(const float*)d_in[17];
    const float *w_mu=(const float*)d_in[18], *b_mu=(const float*)d_in[19];
    const float *w_s =(const float*)d_in[20], *b_s =(const float*)d_in[21];

    float* mu = (float*)d_out;
    float* ls = mu + BB*CC;

    float* S = nullptr;
    cudaGetSymbolAddress((void**)&S, g_scratch);
    float* prev = S;
    float* bi   = S + BB*CC;
    float* h1   = bi + BB*HH;
    float* s2   = h1 + BB*HH;
    float* s3   = s2 + BB*HH;
    float* h2   = s3 + BB*HH;
    float* ob   = h2 + BB*HH;

    cudaFuncSetAttribute(k_pass1, cudaFuncAttributeMaxDynamicSharedMemorySize, P1_SMEM);

    k_init<<<2, 256>>>();
    k_prep<<<64, 256>>>(codes);
    k_pass1<<<dim3(4, (NNPTS + 127) / 128), 256, P1_SMEM>>>(cb);
    k_pass2<<<1024, 256>>>(codes, cb);
    k_gather<<<BB, 64>>>(cb);

    dim3 blk(128);
    dim3 gH(HH/64, BB/64);   // 16 x 8
    dim3 gC(CC/64, BB/64);   // 4 x 8
    k_gemm<true,false><<<gH, blk>>>(prev, nullptr, w_in,  b_in,  bi, CC, HH);
    k_gemm<true,false><<<gH, blk>>>(bi,   nullptr, w_h1,  b_h1,  h1, HH, HH);
    k_gemm<true,false><<<gH, blk>>>(h1,   nullptr, w_s2,  b_s2,  s2, HH, HH);
    k_gemm<true,false><<<gH, blk>>>(h1,   nullptr, w_s3,  b_s3,  s3, HH, HH);
    k_gemm<true,false><<<gH, blk>>>(h1,   s2,      w_h2,  b_h2,  h2, HH, HH);
    k_gemm<true,false><<<gH, blk>>>(h1,   nullptr, w_s1o, b_s1o, ob, HH, HH);
    k_gemm<true,true ><<<gH, blk>>>(h2,   nullptr, w_s2o, b_s2o, ob, HH, HH);
    k_gemm<true,true ><<<gH, blk>>>(h2,   s3,      w_h3,  b_h3,  ob, HH, HH);
    k_gemm<false,false><<<gC, blk>>>(ob,  nullptr, w_mu,  b_mu,  mu, HH, CC);
    k_gemm<false,false><<<gC, blk>>>(ob,  nullptr, w_s,   b_s,   ls, HH, CC);
}